// round 2
// baseline (speedup 1.0000x reference)
#include <cuda_runtime.h>

// Problem constants (fixed by the dataset)
#define BB   2
#define LL   4096
#define CC   1024
#define HH   16
#define DD   64
#define KK   13              // kernel size = sqrt(144)+1
#define NBIA (2*KK - 1)      // 25
#define M_ROWS (BB*LL)       // 8192
#define SCALE  0.125f        // D^-0.5 = 1/8

// Scratch (device globals; no runtime allocation allowed)
__device__ float g_qkv[(size_t)M_ROWS * 3 * CC];   // [B*L, 3C] GEMM-natural layout
__device__ float g_att[(size_t)M_ROWS * CC];       // [B*L, C]

// ---------------------------------------------------------------------------
// SGEMM: Cout[M,N] = A[M,K] @ B[K,N] + bias[N]
// 128x128 block tile, BK=8, 256 threads, 8x8 per-thread register tile.
// M,N,K all multiples of tile dims for this problem (no bounds checks).
// ---------------------------------------------------------------------------
__global__ __launch_bounds__(256) void sgemm_bias_kernel(
    const float* __restrict__ A, const float* __restrict__ B,
    const float* __restrict__ bias, float* __restrict__ Cout,
    int M, int N, int K)
{
    __shared__ float As[8][128];
    __shared__ float Bs[8][128];

    const int tid = threadIdx.x;
    const int bx  = blockIdx.x;   // N tile
    const int by  = blockIdx.y;   // M tile
    const int tx  = tid & 15;     // 0..15  -> 8 cols each
    const int ty  = tid >> 4;     // 0..15  -> 8 rows each

    const int aRow = tid >> 1;          // 0..127
    const int aCol = (tid & 1) * 4;     // 0 or 4
    const int bRow = tid >> 5;          // 0..7
    const int bCol = (tid & 31) * 4;    // 0..124

    const float* Ab = A + (size_t)by * 128 * K;
    const float* Bb = B + (size_t)bx * 128;

    float acc[8][8];
    #pragma unroll
    for (int i = 0; i < 8; i++)
        #pragma unroll
        for (int j = 0; j < 8; j++) acc[i][j] = 0.f;

    for (int k0 = 0; k0 < K; k0 += 8) {
        float4 av = *(const float4*)(Ab + (size_t)aRow * K + k0 + aCol);
        float4 bv = *(const float4*)(Bb + (size_t)(k0 + bRow) * N + bCol);
        __syncthreads();   // previous tile fully consumed before overwrite
        As[aCol + 0][aRow] = av.x;
        As[aCol + 1][aRow] = av.y;
        As[aCol + 2][aRow] = av.z;
        As[aCol + 3][aRow] = av.w;
        *(float4*)(&Bs[bRow][bCol]) = bv;
        __syncthreads();

        #pragma unroll
        for (int k = 0; k < 8; k++) {
            float4 a0 = *(const float4*)(&As[k][ty * 8]);
            float4 a1 = *(const float4*)(&As[k][ty * 8 + 4]);
            float4 b0 = *(const float4*)(&Bs[k][tx * 8]);
            float4 b1 = *(const float4*)(&Bs[k][tx * 8 + 4]);
            float a[8] = {a0.x, a0.y, a0.z, a0.w, a1.x, a1.y, a1.z, a1.w};
            float b[8] = {b0.x, b0.y, b0.z, b0.w, b1.x, b1.y, b1.z, b1.w};
            #pragma unroll
            for (int i = 0; i < 8; i++)
                #pragma unroll
                for (int j = 0; j < 8; j++)
                    acc[i][j] = fmaf(a[i], b[j], acc[i][j]);
        }
    }

    const int colBase = bx * 128 + tx * 8;
    float bs[8];
    #pragma unroll
    for (int j = 0; j < 8; j++) bs[j] = bias[colBase + j];

    #pragma unroll
    for (int i = 0; i < 8; i++) {
        int row = by * 128 + ty * 8 + i;
        float4 o0 = make_float4(acc[i][0] + bs[0], acc[i][1] + bs[1],
                                acc[i][2] + bs[2], acc[i][3] + bs[3]);
        float4 o1 = make_float4(acc[i][4] + bs[4], acc[i][5] + bs[5],
                                acc[i][6] + bs[6], acc[i][7] + bs[7]);
        float* cp = Cout + (size_t)row * N + colBase;
        *(float4*)(cp)     = o0;
        *(float4*)(cp + 4) = o1;
    }
}

// ---------------------------------------------------------------------------
// Neighborhood attention: one warp per (b, h, l).
// qkv layout: [(b*L + l), which*C + h*D + d], which in {0=q,1=k,2=v}
// out layout: g_att[(b*L + l)*C + h*D + d]   (proj-GEMM ready)
// ---------------------------------------------------------------------------
__global__ __launch_bounds__(256) void natt_kernel(const float* __restrict__ rpb)
{
    const int gid  = blockIdx.x * blockDim.x + threadIdx.x;
    const int lane = gid & 31;
    const int gw   = gid >> 5;          // 0 .. B*H*L-1
    const int l    = gw % LL;
    const int h    = (gw / LL) % HH;
    const int b    = gw / (LL * HH);

    int start = l - KK / 2;
    if (start < 0) start = 0;
    if (start > LL - KK) start = LL - KK;

    const size_t rowStride = (size_t)3 * CC;
    const float* q_ptr = g_qkv + (size_t)(b * LL + l) * rowStride + h * DD;
    const float2 q2 = ((const float2*)q_ptr)[lane];

    // scores
    float s[KK];
    #pragma unroll
    for (int j = 0; j < KK; j++) {
        const int idx = start + j;
        const float* k_ptr = g_qkv + (size_t)(b * LL + idx) * rowStride + CC + h * DD;
        const float2 k2 = ((const float2*)k_ptr)[lane];
        float p = q2.x * k2.x + q2.y * k2.y;
        #pragma unroll
        for (int m = 16; m > 0; m >>= 1)
            p += __shfl_xor_sync(0xffffffff, p, m);
        s[j] = p * SCALE + rpb[h * NBIA + (idx - l + KK - 1)];
    }

    // softmax over KK (replicated across lanes)
    float mx = s[0];
    #pragma unroll
    for (int j = 1; j < KK; j++) mx = fmaxf(mx, s[j]);
    float denom = 0.f;
    #pragma unroll
    for (int j = 0; j < KK; j++) { s[j] = expf(s[j] - mx); denom += s[j]; }
    const float inv = 1.f / denom;

    // weighted V sum
    float2 acc = make_float2(0.f, 0.f);
    #pragma unroll
    for (int j = 0; j < KK; j++) {
        const int idx = start + j;
        const float* v_ptr = g_qkv + (size_t)(b * LL + idx) * rowStride + 2 * CC + h * DD;
        const float2 v2 = ((const float2*)v_ptr)[lane];
        const float p = s[j] * inv;
        acc.x = fmaf(p, v2.x, acc.x);
        acc.y = fmaf(p, v2.y, acc.y);
    }

    float* o_ptr = g_att + (size_t)(b * LL + l) * CC + h * DD;
    ((float2*)o_ptr)[lane] = acc;
}

// ---------------------------------------------------------------------------
extern "C" void kernel_launch(void* const* d_in, const int* in_sizes, int n_in,
                              void* d_out, int out_size)
{
    const float* x      = (const float*)d_in[0];  // [B,L,C]
    const float* w_qkv  = (const float*)d_in[1];  // [C,3C]
    const float* b_qkv  = (const float*)d_in[2];  // [3C]
    const float* rpb    = (const float*)d_in[3];  // [H,25]
    const float* w_proj = (const float*)d_in[4];  // [C,C]
    const float* b_proj = (const float*)d_in[5];  // [C]
    float*       out    = (float*)d_out;          // [B,L,C]

    float* qkv_buf = nullptr;
    float* att_buf = nullptr;
    cudaGetSymbolAddress((void**)&qkv_buf, g_qkv);
    cudaGetSymbolAddress((void**)&att_buf, g_att);

    // 1) QKV projection: [8192,1024] @ [1024,3072] + bias
    {
        dim3 grid(3 * CC / 128, M_ROWS / 128);
        sgemm_bias_kernel<<<grid, 256>>>(x, w_qkv, b_qkv, qkv_buf,
                                         M_ROWS, 3 * CC, CC);
    }

    // 2) neighborhood attention: one warp per (b,h,l)
    {
        const int totalWarps = BB * HH * LL;
        dim3 grid(totalWarps * 32 / 256);
        natt_kernel<<<grid, 256>>>(rpb);
    }

    // 3) output projection: [8192,1024] @ [1024,1024] + bias
    {
        dim3 grid(CC / 128, M_ROWS / 128);
        sgemm_bias_kernel<<<grid, 256>>>(att_buf, w_proj, b_proj, out,
                                         M_ROWS, CC, CC);
    }
}

// round 3
// speedup vs baseline: 1.6008x; 1.6008x over previous
#include <cuda_runtime.h>
#include <mma.h>
using namespace nvcuda;

// Problem constants (fixed by the dataset)
#define BB   2
#define LL   4096
#define CC   1024
#define HH   16
#define DD   64
#define KK   13              // kernel size = sqrt(144)+1
#define NBIA (2*KK - 1)      // 25
#define M_ROWS (BB*LL)       // 8192
#define SCALE  0.125f        // D^-0.5 = 1/8

// Scratch (device globals; no runtime allocation allowed)
__device__ float g_qkv[(size_t)M_ROWS * 3 * CC];   // [B*L, 3C]
__device__ float g_att[(size_t)M_ROWS * CC];       // [B*L, C]

// ---------------------------------------------------------------------------
// TF32 tensor-core GEMM: Cout[M,N] = A[M,K] @ B[K,N] + bias[N]
// 128x128 block tile, BK=32, 256 threads (8 warps in 4x2 layout),
// each warp owns a 32x64 tile = 2x4 wmma 16x16x8 accumulators.
// M % 128 == 0, N % 128 == 0, K % 32 == 0 for this problem.
// ---------------------------------------------------------------------------
#define BM 128
#define BN 128
#define BK 32
#define PAD_A 4
#define PAD_B 4
#define LDA_S (BK + PAD_A)    // 36
#define LDB_S (BN + PAD_B)    // 132

__global__ __launch_bounds__(256) void tf32_gemm_bias_kernel(
    const float* __restrict__ A, const float* __restrict__ B,
    const float* __restrict__ bias, float* __restrict__ Cout,
    int M, int N, int K)
{
    __shared__ float As[BM][LDA_S];      // 18.4 KB
    __shared__ float Bs[BK][LDB_S];      // 16.9 KB
    __shared__ float BiasS[16][LDB_S];   //  8.4 KB  (16 identical rows of bias)

    const int tid    = threadIdx.x;
    const int warpId = tid >> 5;
    const int warp_m = warpId & 3;       // 0..3  -> 32-row slab
    const int warp_n = warpId >> 2;      // 0..1  -> 64-col slab
    const int bx = blockIdx.x;           // N tile
    const int by = blockIdx.y;           // M tile

    // Fill the replicated bias tile (16 rows x 128 cols)
    {
        const float* bsrc = bias + bx * BN;
        for (int idx = tid; idx < 16 * BN; idx += 256) {
            int r = idx >> 7;            // /128
            int c = idx & 127;
            BiasS[r][c] = bsrc[c];
        }
    }
    __syncthreads();

    // Accumulators initialized from the bias tile (layout-agnostic)
    wmma::fragment<wmma::accumulator, 16, 16, 8, float> acc[2][4];
    #pragma unroll
    for (int i = 0; i < 2; i++)
        #pragma unroll
        for (int j = 0; j < 4; j++)
            wmma::load_matrix_sync(acc[i][j], &BiasS[0][warp_n * 64 + j * 16],
                                   LDB_S, wmma::mem_row_major);

    const float* Ab = A + (size_t)by * BM * K;
    const float* Bb = B + (size_t)bx * BN;

    // gmem load mapping
    const int aRow0 = tid >> 3;          // 0..31, step 32 -> 128 rows
    const int aCol  = (tid & 7) * 4;     // 0..28
    const int bRow0 = tid >> 5;          // 0..7, step 8 -> 32 rows
    const int bCol  = (tid & 31) * 4;    // 0..124

    for (int k0 = 0; k0 < K; k0 += BK) {
        // ---- load tiles into smem ----
        float4 aReg[4], bReg[4];
        #pragma unroll
        for (int i = 0; i < 4; i++)
            aReg[i] = *(const float4*)(Ab + (size_t)(aRow0 + 32 * i) * K + k0 + aCol);
        #pragma unroll
        for (int i = 0; i < 4; i++)
            bReg[i] = *(const float4*)(Bb + (size_t)(k0 + bRow0 + 8 * i) * N + bCol);
        __syncthreads();
        #pragma unroll
        for (int i = 0; i < 4; i++)
            *(float4*)(&As[aRow0 + 32 * i][aCol]) = aReg[i];
        #pragma unroll
        for (int i = 0; i < 4; i++)
            *(float4*)(&Bs[bRow0 + 8 * i][bCol]) = bReg[i];
        __syncthreads();

        // ---- 4 k-steps of 8 ----
        #pragma unroll
        for (int ks = 0; ks < BK / 8; ks++) {
            wmma::fragment<wmma::matrix_a, 16, 16, 8, wmma::precision::tf32,
                           wmma::row_major> afrag[2];
            wmma::fragment<wmma::matrix_b, 16, 16, 8, wmma::precision::tf32,
                           wmma::row_major> bfrag[4];
            #pragma unroll
            for (int i = 0; i < 2; i++) {
                wmma::load_matrix_sync(afrag[i],
                    &As[warp_m * 32 + i * 16][ks * 8], LDA_S);
                #pragma unroll
                for (int t = 0; t < afrag[i].num_elements; t++)
                    afrag[i].x[t] = wmma::__float_to_tf32(afrag[i].x[t]);
            }
            #pragma unroll
            for (int j = 0; j < 4; j++) {
                wmma::load_matrix_sync(bfrag[j],
                    &Bs[ks * 8][warp_n * 64 + j * 16], LDB_S);
                #pragma unroll
                for (int t = 0; t < bfrag[j].num_elements; t++)
                    bfrag[j].x[t] = wmma::__float_to_tf32(bfrag[j].x[t]);
            }
            #pragma unroll
            for (int i = 0; i < 2; i++)
                #pragma unroll
                for (int j = 0; j < 4; j++)
                    wmma::mma_sync(acc[i][j], afrag[i], bfrag[j], acc[i][j]);
        }
    }

    // ---- epilogue: direct store (bias already inside acc) ----
    #pragma unroll
    for (int i = 0; i < 2; i++) {
        const int row = by * BM + warp_m * 32 + i * 16;
        #pragma unroll
        for (int j = 0; j < 4; j++) {
            const int col = bx * BN + warp_n * 64 + j * 16;
            wmma::store_matrix_sync(Cout + (size_t)row * N + col, acc[i][j],
                                    N, wmma::mem_row_major);
        }
    }
}

// ---------------------------------------------------------------------------
// Neighborhood attention: one warp per (b, h, l). (unchanged, exact fp32)
// qkv layout: [(b*L + l), which*C + h*D + d], which in {0=q,1=k,2=v}
// ---------------------------------------------------------------------------
__global__ __launch_bounds__(256) void natt_kernel(const float* __restrict__ rpb)
{
    const int gid  = blockIdx.x * blockDim.x + threadIdx.x;
    const int lane = gid & 31;
    const int gw   = gid >> 5;          // 0 .. B*H*L-1
    const int l    = gw % LL;
    const int h    = (gw / LL) % HH;
    const int b    = gw / (LL * HH);

    int start = l - KK / 2;
    if (start < 0) start = 0;
    if (start > LL - KK) start = LL - KK;

    const size_t rowStride = (size_t)3 * CC;
    const float* q_ptr = g_qkv + (size_t)(b * LL + l) * rowStride + h * DD;
    const float2 q2 = ((const float2*)q_ptr)[lane];

    float s[KK];
    #pragma unroll
    for (int j = 0; j < KK; j++) {
        const int idx = start + j;
        const float* k_ptr = g_qkv + (size_t)(b * LL + idx) * rowStride + CC + h * DD;
        const float2 k2 = ((const float2*)k_ptr)[lane];
        float p = q2.x * k2.x + q2.y * k2.y;
        #pragma unroll
        for (int m = 16; m > 0; m >>= 1)
            p += __shfl_xor_sync(0xffffffff, p, m);
        s[j] = p * SCALE + rpb[h * NBIA + (idx - l + KK - 1)];
    }

    float mx = s[0];
    #pragma unroll
    for (int j = 1; j < KK; j++) mx = fmaxf(mx, s[j]);
    float denom = 0.f;
    #pragma unroll
    for (int j = 0; j < KK; j++) { s[j] = expf(s[j] - mx); denom += s[j]; }
    const float inv = 1.f / denom;

    float2 acc = make_float2(0.f, 0.f);
    #pragma unroll
    for (int j = 0; j < KK; j++) {
        const int idx = start + j;
        const float* v_ptr = g_qkv + (size_t)(b * LL + idx) * rowStride + 2 * CC + h * DD;
        const float2 v2 = ((const float2*)v_ptr)[lane];
        const float p = s[j] * inv;
        acc.x = fmaf(p, v2.x, acc.x);
        acc.y = fmaf(p, v2.y, acc.y);
    }

    float* o_ptr = g_att + (size_t)(b * LL + l) * CC + h * DD;
    ((float2*)o_ptr)[lane] = acc;
}

// ---------------------------------------------------------------------------
extern "C" void kernel_launch(void* const* d_in, const int* in_sizes, int n_in,
                              void* d_out, int out_size)
{
    const float* x      = (const float*)d_in[0];  // [B,L,C]
    const float* w_qkv  = (const float*)d_in[1];  // [C,3C]
    const float* b_qkv  = (const float*)d_in[2];  // [3C]
    const float* rpb    = (const float*)d_in[3];  // [H,25]
    const float* w_proj = (const float*)d_in[4];  // [C,C]
    const float* b_proj = (const float*)d_in[5];  // [C]
    float*       out    = (float*)d_out;          // [B,L,C]

    float* qkv_buf = nullptr;
    float* att_buf = nullptr;
    cudaGetSymbolAddress((void**)&qkv_buf, g_qkv);
    cudaGetSymbolAddress((void**)&att_buf, g_att);

    // 1) QKV projection: [8192,1024] @ [1024,3072] + bias  (tensor cores, TF32)
    {
        dim3 grid(3 * CC / BN, M_ROWS / BM);
        tf32_gemm_bias_kernel<<<grid, 256>>>(x, w_qkv, b_qkv, qkv_buf,
                                             M_ROWS, 3 * CC, CC);
    }

    // 2) neighborhood attention: one warp per (b,h,l)
    {
        const int totalWarps = BB * HH * LL;
        dim3 grid(totalWarps * 32 / 256);
        natt_kernel<<<grid, 256>>>(rpb);
    }

    // 3) output projection: [8192,1024] @ [1024,1024] + bias  (tensor cores, TF32)
    {
        dim3 grid(CC / BN, M_ROWS / BM);
        tf32_gemm_bias_kernel<<<grid, 256>>>(att_buf, w_proj, b_proj, out,
                                             M_ROWS, CC, CC);
    }
}

// round 4
// speedup vs baseline: 1.6135x; 1.0079x over previous
#include <cuda_runtime.h>
#include <mma.h>
using namespace nvcuda;

// Problem constants (fixed by the dataset)
#define BB   2
#define LL   4096
#define CC   1024
#define HH   16
#define DD   64
#define KK   13              // kernel size = sqrt(144)+1
#define NBIA (2*KK - 1)      // 25
#define M_ROWS (BB*LL)       // 8192
#define SCALE  0.125f        // D^-0.5 = 1/8

// Scratch (device globals; no runtime allocation allowed)
__device__ float g_qkv[(size_t)M_ROWS * 3 * CC];   // [B*L, 3C]
__device__ float g_att[(size_t)M_ROWS * CC];       // [B*L, C]

// ---------------------------------------------------------------------------
// TF32 tensor-core GEMM: Cout[M,N] = A[M,K] @ B[K,N] + bias[N]
// 128x128 block tile, BK=32, 256 threads (8 warps in 4x2 layout),
// each warp owns a 32x64 tile = 2x4 wmma 16x16x8 accumulators.
// M % 128 == 0, N % 128 == 0, K % 32 == 0 for this problem.
// ---------------------------------------------------------------------------
#define BM 128
#define BN 128
#define BK 32
#define PAD_A 4
#define PAD_B 4
#define LDA_S (BK + PAD_A)    // 36
#define LDB_S (BN + PAD_B)    // 132

__global__ __launch_bounds__(256) void tf32_gemm_bias_kernel(
    const float* __restrict__ A, const float* __restrict__ B,
    const float* __restrict__ bias, float* __restrict__ Cout,
    int M, int N, int K)
{
    __shared__ float As[BM][LDA_S];      // 18.4 KB
    __shared__ float Bs[BK][LDB_S];      // 16.9 KB
    __shared__ float BiasS[16][LDB_S];   //  8.4 KB  (16 identical rows of bias)

    const int tid    = threadIdx.x;
    const int warpId = tid >> 5;
    const int warp_m = warpId & 3;       // 0..3  -> 32-row slab
    const int warp_n = warpId >> 2;      // 0..1  -> 64-col slab
    const int bx = blockIdx.x;           // N tile
    const int by = blockIdx.y;           // M tile

    // Fill the replicated bias tile (16 rows x 128 cols)
    {
        const float* bsrc = bias + bx * BN;
        for (int idx = tid; idx < 16 * BN; idx += 256) {
            int r = idx >> 7;            // /128
            int c = idx & 127;
            BiasS[r][c] = bsrc[c];
        }
    }
    __syncthreads();

    // Accumulators initialized from the bias tile (layout-agnostic)
    wmma::fragment<wmma::accumulator, 16, 16, 8, float> acc[2][4];
    #pragma unroll
    for (int i = 0; i < 2; i++)
        #pragma unroll
        for (int j = 0; j < 4; j++)
            wmma::load_matrix_sync(acc[i][j], &BiasS[0][warp_n * 64 + j * 16],
                                   LDB_S, wmma::mem_row_major);

    const float* Ab = A + (size_t)by * BM * K;
    const float* Bb = B + (size_t)bx * BN;

    // gmem load mapping
    const int aRow0 = tid >> 3;          // 0..31, step 32 -> 128 rows
    const int aCol  = (tid & 7) * 4;     // 0..28
    const int bRow0 = tid >> 5;          // 0..7, step 8 -> 32 rows
    const int bCol  = (tid & 31) * 4;    // 0..124

    for (int k0 = 0; k0 < K; k0 += BK) {
        // ---- load tiles into smem ----
        float4 aReg[4], bReg[4];
        #pragma unroll
        for (int i = 0; i < 4; i++)
            aReg[i] = *(const float4*)(Ab + (size_t)(aRow0 + 32 * i) * K + k0 + aCol);
        #pragma unroll
        for (int i = 0; i < 4; i++)
            bReg[i] = *(const float4*)(Bb + (size_t)(k0 + bRow0 + 8 * i) * N + bCol);
        __syncthreads();
        #pragma unroll
        for (int i = 0; i < 4; i++)
            *(float4*)(&As[aRow0 + 32 * i][aCol]) = aReg[i];
        #pragma unroll
        for (int i = 0; i < 4; i++)
            *(float4*)(&Bs[bRow0 + 8 * i][bCol]) = bReg[i];
        __syncthreads();

        // ---- 4 k-steps of 8 ----
        #pragma unroll
        for (int ks = 0; ks < BK / 8; ks++) {
            wmma::fragment<wmma::matrix_a, 16, 16, 8, wmma::precision::tf32,
                           wmma::row_major> afrag[2];
            wmma::fragment<wmma::matrix_b, 16, 16, 8, wmma::precision::tf32,
                           wmma::row_major> bfrag[4];
            #pragma unroll
            for (int i = 0; i < 2; i++) {
                wmma::load_matrix_sync(afrag[i],
                    &As[warp_m * 32 + i * 16][ks * 8], LDA_S);
                #pragma unroll
                for (int t = 0; t < afrag[i].num_elements; t++)
                    afrag[i].x[t] = wmma::__float_to_tf32(afrag[i].x[t]);
            }
            #pragma unroll
            for (int j = 0; j < 4; j++) {
                wmma::load_matrix_sync(bfrag[j],
                    &Bs[ks * 8][warp_n * 64 + j * 16], LDB_S);
                #pragma unroll
                for (int t = 0; t < bfrag[j].num_elements; t++)
                    bfrag[j].x[t] = wmma::__float_to_tf32(bfrag[j].x[t]);
            }
            #pragma unroll
            for (int i = 0; i < 2; i++)
                #pragma unroll
                for (int j = 0; j < 4; j++)
                    wmma::mma_sync(acc[i][j], afrag[i], bfrag[j], acc[i][j]);
        }
    }

    // ---- epilogue: direct store (bias already inside acc) ----
    #pragma unroll
    for (int i = 0; i < 2; i++) {
        const int row = by * BM + warp_m * 32 + i * 16;
        #pragma unroll
        for (int j = 0; j < 4; j++) {
            const int col = bx * BN + warp_n * 64 + j * 16;
            wmma::store_matrix_sync(Cout + (size_t)row * N + col, acc[i][j],
                                    N, wmma::mem_row_major);
        }
    }
}

// ---------------------------------------------------------------------------
// Neighborhood attention: one warp per (b, h, l). (unchanged, exact fp32)
// qkv layout: [(b*L + l), which*C + h*D + d], which in {0=q,1=k,2=v}
// ---------------------------------------------------------------------------
__global__ __launch_bounds__(256) void natt_kernel(const float* __restrict__ rpb)
{
    const int gid  = blockIdx.x * blockDim.x + threadIdx.x;
    const int lane = gid & 31;
    const int gw   = gid >> 5;          // 0 .. B*H*L-1
    const int l    = gw % LL;
    const int h    = (gw / LL) % HH;
    const int b    = gw / (LL * HH);

    int start = l - KK / 2;
    if (start < 0) start = 0;
    if (start > LL - KK) start = LL - KK;

    const size_t rowStride = (size_t)3 * CC;
    const float* q_ptr = g_qkv + (size_t)(b * LL + l) * rowStride + h * DD;
    const float2 q2 = ((const float2*)q_ptr)[lane];

    float s[KK];
    #pragma unroll
    for (int j = 0; j < KK; j++) {
        const int idx = start + j;
        const float* k_ptr = g_qkv + (size_t)(b * LL + idx) * rowStride + CC + h * DD;
        const float2 k2 = ((const float2*)k_ptr)[lane];
        float p = q2.x * k2.x + q2.y * k2.y;
        #pragma unroll
        for (int m = 16; m > 0; m >>= 1)
            p += __shfl_xor_sync(0xffffffff, p, m);
        s[j] = p * SCALE + rpb[h * NBIA + (idx - l + KK - 1)];
    }

    float mx = s[0];
    #pragma unroll
    for (int j = 1; j < KK; j++) mx = fmaxf(mx, s[j]);
    float denom = 0.f;
    #pragma unroll
    for (int j = 0; j < KK; j++) { s[j] = expf(s[j] - mx); denom += s[j]; }
    const float inv = 1.f / denom;

    float2 acc = make_float2(0.f, 0.f);
    #pragma unroll
    for (int j = 0; j < KK; j++) {
        const int idx = start + j;
        const float* v_ptr = g_qkv + (size_t)(b * LL + idx) * rowStride + 2 * CC + h * DD;
        const float2 v2 = ((const float2*)v_ptr)[lane];
        const float p = s[j] * inv;
        acc.x = fmaf(p, v2.x, acc.x);
        acc.y = fmaf(p, v2.y, acc.y);
    }

    float* o_ptr = g_att + (size_t)(b * LL + l) * CC + h * DD;
    ((float2*)o_ptr)[lane] = acc;
}

// ---------------------------------------------------------------------------
extern "C" void kernel_launch(void* const* d_in, const int* in_sizes, int n_in,
                              void* d_out, int out_size)
{
    const float* x      = (const float*)d_in[0];  // [B,L,C]
    const float* w_qkv  = (const float*)d_in[1];  // [C,3C]
    const float* b_qkv  = (const float*)d_in[2];  // [3C]
    const float* rpb    = (const float*)d_in[3];  // [H,25]
    const float* w_proj = (const float*)d_in[4];  // [C,C]
    const float* b_proj = (const float*)d_in[5];  // [C]
    float*       out    = (float*)d_out;          // [B,L,C]

    float* qkv_buf = nullptr;
    float* att_buf = nullptr;
    cudaGetSymbolAddress((void**)&qkv_buf, g_qkv);
    cudaGetSymbolAddress((void**)&att_buf, g_att);

    // 1) QKV projection: [8192,1024] @ [1024,3072] + bias  (tensor cores, TF32)
    {
        dim3 grid(3 * CC / BN, M_ROWS / BM);
        tf32_gemm_bias_kernel<<<grid, 256>>>(x, w_qkv, b_qkv, qkv_buf,
                                             M_ROWS, 3 * CC, CC);
    }

    // 2) neighborhood attention: one warp per (b,h,l)
    {
        const int totalWarps = BB * HH * LL;
        dim3 grid(totalWarps * 32 / 256);
        natt_kernel<<<grid, 256>>>(rpb);
    }

    // 3) output projection: [8192,1024] @ [1024,1024] + bias  (tensor cores, TF32)
    {
        dim3 grid(CC / BN, M_ROWS / BM);
        tf32_gemm_bias_kernel<<<grid, 256>>>(att_buf, w_proj, b_proj, out,
                                             M_ROWS, CC, CC);
    }
}